// round 9
// baseline (speedup 1.0000x reference)
#include <cuda_runtime.h>
#include <cuda_fp16.h>
#include <cstdint>

#define BATCH 32
#define DIM   128
#define TLEN  4096
#define SZ    512

// ---- smem byte map ----
#define SM_MB0   0
#define SM_MB1   8
#define SM_MBE0  16
#define SM_MBE1  24
#define SM_M2    128      // 512 floats
#define SM_PSUM  2176     // 8*64 floats
#define SM_CSUM  4224     // 64 floats (stores 1/sum)
#define SM_A     7168     // [2 comp][128 k][72 halfs]  = 36864 B  (hi @ +0, lo @ +18432)
#define SM_B     44032    // [2 buf][2 comp][512 s][40 halfs] = 163840 B
#define SM_TOTAL 207872
// epilogue stage reuses SM_B: [512 s][68 floats] = 139264 B

// global prep images: [4 kc][2 comp][512 s][40 halfs]
__device__ __align__(128) unsigned char gUimgB[327680];
__device__ float g_m2[SZ];

__device__ __forceinline__ uint32_t smem_u32(const void* p) {
    uint32_t a;
    asm("{ .reg .u64 t; cvta.to.shared.u64 t, %1; cvt.u32.u64 %0, t; }" : "=r"(a) : "l"(p));
    return a;
}
#define MBAR_INIT(a,n)   asm volatile("mbarrier.init.shared.b64 [%0], %1;" ::"r"(a),"r"(n):"memory")
#define MBAR_EXPECT(a,b) asm volatile("mbarrier.arrive.expect_tx.shared.b64 _, [%0], %1;" ::"r"(a),"r"(b):"memory")
#define MBAR_ARRIVE(a)   asm volatile("mbarrier.arrive.release.cta.shared::cta.b64 _, [%0];" ::"r"(a):"memory")
__device__ __forceinline__ void mbar_wait(uint32_t mbar, uint32_t parity) {
    uint32_t done;
    asm volatile("{ .reg .pred p; mbarrier.try_wait.parity.acquire.cta.shared::cta.b64 p, [%1], %2; selp.b32 %0,1,0,p; }"
                 : "=r"(done) : "r"(mbar), "r"(parity) : "memory");
    if (!done) {
        asm volatile("{ .reg .pred P1; W_%=: mbarrier.try_wait.parity.acquire.cta.shared::cta.b64 P1, [%0], %1, 0x989680;\n\t"
                     "@P1 bra.uni D_%=; bra.uni W_%=; D_%=: }" :: "r"(mbar), "r"(parity) : "memory");
    }
}
__device__ __forceinline__ void bulk_g2s(uint32_t dst, const void* src, uint32_t bytes, uint32_t mbar) {
    uint64_t g = (uint64_t)__cvta_generic_to_global(src);
    asm volatile("cp.async.bulk.shared::cta.global.mbarrier::complete_tx::bytes [%0], [%1], %2, [%3];"
                 :: "r"(dst), "l"(g), "r"(bytes), "r"(mbar) : "memory");
}
__device__ __forceinline__ void ldsm4t(uint32_t* r, uint32_t a) {
    asm volatile("ldmatrix.sync.aligned.m8n8.x4.trans.shared.b16 {%0,%1,%2,%3}, [%4];"
                 : "=r"(r[0]),"=r"(r[1]),"=r"(r[2]),"=r"(r[3]) : "r"(a));
}
__device__ __forceinline__ void ldsm4(uint32_t* r, uint32_t a) {
    asm volatile("ldmatrix.sync.aligned.m8n8.x4.shared.b16 {%0,%1,%2,%3}, [%4];"
                 : "=r"(r[0]),"=r"(r[1]),"=r"(r[2]),"=r"(r[3]) : "r"(a));
}
__device__ __forceinline__ void mma16816(float* d, const uint32_t* a, const uint32_t* b) {
    asm volatile("mma.sync.aligned.m16n8k16.row.col.f32.f16.f16.f32 "
                 "{%0,%1,%2,%3}, {%4,%5,%6,%7}, {%8,%9}, {%0,%1,%2,%3};"
                 : "+f"(d[0]),"+f"(d[1]),"+f"(d[2]),"+f"(d[3])
                 : "r"(a[0]),"r"(a[1]),"r"(a[2]),"r"(a[3]), "r"(b[0]),"r"(b[1]));
}

// ---- merged prep: hi/lo image + m2, 512 blocks (one s each) x 128 threads ----
__global__ void prep_kernel(const float* __restrict__ units) {
    const int s = blockIdx.x, k = threadIdx.x;
    const int lane = k & 31;
    float x = units[k * SZ + s];
    __half hi = __float2half_rn(x);
    __half lo = __float2half_rn(x - __half2float(hi));
    int kc = k >> 5, kl = k & 31;
    __half* base = (__half*)gUimgB;
    base[((kc * 2 + 0) * 512 + s) * 40 + kl] = hi;
    base[((kc * 2 + 1) * 512 + s) * 40 + kl] = lo;

    float v = x * x;
    #pragma unroll
    for (int o = 16; o > 0; o >>= 1) v += __shfl_xor_sync(0xffffffffu, v, o);
    __shared__ float ps[4];
    if (lane == 0) ps[k >> 5] = v;
    __syncthreads();
    if (k == 0) g_m2[s] = ps[0] + ps[1] + ps[2] + ps[3];
}

__global__ __launch_bounds__(512, 1)
void mb_kernel(const float* __restrict__ H, float* __restrict__ out) {
    extern __shared__ __align__(128) unsigned char smem[];
    const uint32_t sb = smem_u32(smem);
    const int tid = threadIdx.x, w = tid >> 5, lane = tid & 31;
    const int r = lane >> 2, q = lane & 3;
    const int wt = w & 1, ws = w >> 1;          // t-half, s-group
    const int b = blockIdx.y, tb = blockIdx.x * 64;

    if (tid == 0) {
        MBAR_INIT(sb + SM_MB0, 1);
        MBAR_INIT(sb + SM_MB1, 1);
        MBAR_INIT(sb + SM_MBE0, 16);
        MBAR_INIT(sb + SM_MBE1, 16);
        MBAR_EXPECT(sb + SM_MB0, 81920);
        bulk_g2s(sb + SM_B,         gUimgB,         81920, sb + SM_MB0);
        MBAR_EXPECT(sb + SM_MB1, 81920);
        bulk_g2s(sb + SM_B + 81920, gUimgB + 81920, 81920, sb + SM_MB1);
    }

    // m2 -> smem
    ((float*)(smem + SM_M2))[tid] = g_m2[tid];

    // ---- H tile (128 k x 64 t fp32) -> split f16 hi/lo -> A smem [comp][k][72] ----
    const float* Hb = H + (size_t)b * DIM * TLEN;
    #pragma unroll
    for (int i = 0; i < 4; ++i) {
        int f4 = i * 512 + tid;          // 0..2047
        int k = f4 >> 4, t0 = (f4 & 15) * 4;
        float4 v = *reinterpret_cast<const float4*>(&Hb[(size_t)k * TLEN + tb + t0]);
        float xs[4] = {v.x, v.y, v.z, v.w};
        uint32_t hiw[2], low[2];
        #pragma unroll
        for (int j = 0; j < 2; ++j) {
            __half h0 = __float2half_rn(xs[2*j]);
            __half h1 = __float2half_rn(xs[2*j+1]);
            __half l0 = __float2half_rn(xs[2*j]   - __half2float(h0));
            __half l1 = __float2half_rn(xs[2*j+1] - __half2float(h1));
            hiw[j] = (uint32_t)__half_as_ushort(h0) | ((uint32_t)__half_as_ushort(h1) << 16);
            low[j] = (uint32_t)__half_as_ushort(l0) | ((uint32_t)__half_as_ushort(l1) << 16);
        }
        *reinterpret_cast<uint2*>(smem + SM_A +         k * 144 + t0 * 2) = make_uint2(hiw[0], hiw[1]);
        *reinterpret_cast<uint2*>(smem + SM_A + 18432 + k * 144 + t0 * 2) = make_uint2(low[0], low[1]);
    }
    __syncthreads();   // A visible + mbarriers initialized for all warps

    // ---- MMA main loop: warp tile = 32 t x 64 s ----
    float acc[2][8][4];
    #pragma unroll
    for (int mi = 0; mi < 2; ++mi)
        #pragma unroll
        for (int ni = 0; ni < 8; ++ni)
            #pragma unroll
            for (int c = 0; c < 4; ++c) acc[mi][ni][c] = 0.f;

    const int lr = lane & 7;
    const uint32_t kAdd = (lane & 16) ? 8u : 0u;
    const uint32_t g1   = (lane & 8)  ? 8u : 0u;

    #pragma unroll 1
    for (int kc = 0; kc < 4; ++kc) {
        const int buf = kc & 1;
        const uint32_t mbF = sb + (buf ? SM_MB1  : SM_MB0);
        const uint32_t mbE = sb + (buf ? SM_MBE1 : SM_MBE0);
        mbar_wait(mbF, kc >> 1);
        const uint32_t bBuf = sb + SM_B + buf * 81920;

        #pragma unroll
        for (int ks = 0; ks < 2; ++ks) {
            const int k0g = kc * 32 + ks * 16;
            const int kl0 = ks * 16;
            uint32_t afh[2][4], afl[2][4], bfh[4][4], bfl[4][4];

            #pragma unroll
            for (int mi = 0; mi < 2; ++mi)
                ldsm4t(afh[mi], sb + SM_A + (k0g + lr + kAdd) * 144 + (32*wt + 16*mi + g1) * 2);
            #pragma unroll
            for (int j = 0; j < 4; ++j)
                ldsm4(bfh[j], bBuf + (64*ws + 16*j + lr + kAdd) * 80 + (kl0 + g1) * 2);
            // p0: Ah x Bh
            #pragma unroll
            for (int mi = 0; mi < 2; ++mi)
                #pragma unroll
                for (int j = 0; j < 4; ++j) {
                    mma16816(acc[mi][2*j],     afh[mi], &bfh[j][0]);
                    mma16816(acc[mi][2*j + 1], afh[mi], &bfh[j][2]);
                }
            // B lo
            #pragma unroll
            for (int j = 0; j < 4; ++j)
                ldsm4(bfl[j], bBuf + 40960 + (64*ws + 16*j + lr + kAdd) * 80 + (kl0 + g1) * 2);
            // p1: Ah x Bl
            #pragma unroll
            for (int mi = 0; mi < 2; ++mi)
                #pragma unroll
                for (int j = 0; j < 4; ++j) {
                    mma16816(acc[mi][2*j],     afh[mi], &bfl[j][0]);
                    mma16816(acc[mi][2*j + 1], afh[mi], &bfl[j][2]);
                }
            // A lo
            #pragma unroll
            for (int mi = 0; mi < 2; ++mi)
                ldsm4t(afl[mi], sb + SM_A + 18432 + (k0g + lr + kAdd) * 144 + (32*wt + 16*mi + g1) * 2);
            // p2: Al x Bh
            #pragma unroll
            for (int mi = 0; mi < 2; ++mi)
                #pragma unroll
                for (int j = 0; j < 4; ++j) {
                    mma16816(acc[mi][2*j],     afl[mi], &bfh[j][0]);
                    mma16816(acc[mi][2*j + 1], afl[mi], &bfh[j][2]);
                }
        }
        if (lane == 0) MBAR_ARRIVE(mbE);
        if (tid == 0 && kc < 2) {
            mbar_wait(mbE, 0);
            MBAR_EXPECT(mbF, 81920);
            bulk_g2s(sb + SM_B + buf * 81920, gUimgB + (kc + 2) * 81920, 81920, mbF);
        }
    }

    // ---- epilogue: exp (no max-sub; |logit| bounded) -> sum -> scale ----
    const float* m2s = (const float*)(smem + SM_M2);
    float* psum = (float*)(smem + SM_PSUM);
    float* cinv = (float*)(smem + SM_CSUM);

    float m2v[8][2];
    #pragma unroll
    for (int ni = 0; ni < 8; ++ni) {
        m2v[ni][0] = m2s[64*ws + 8*ni + 2*q];
        m2v[ni][1] = m2s[64*ws + 8*ni + 2*q + 1];
    }

    #pragma unroll
    for (int mi = 0; mi < 2; ++mi)
        #pragma unroll
        for (int h = 0; h < 2; ++h) {
            float s = 0.f;
            #pragma unroll
            for (int ni = 0; ni < 8; ++ni) {
                float e0 = __expf(fmaf(2.f, acc[mi][ni][2*h],     -m2v[ni][0]));
                float e1 = __expf(fmaf(2.f, acc[mi][ni][2*h + 1], -m2v[ni][1]));
                acc[mi][ni][2*h] = e0; acc[mi][ni][2*h + 1] = e1;
                s += e0 + e1;
            }
            s += __shfl_xor_sync(0xffffffffu, s, 1);
            s += __shfl_xor_sync(0xffffffffu, s, 2);
            if (q == 0) psum[ws * 64 + 32*wt + 16*mi + r + 8*h] = s;
        }
    __syncthreads();   // also guarantees all warps finished mainloop
    if (tid < 64) {
        float s = psum[tid];
        #pragma unroll
        for (int g = 1; g < 8; ++g) s += psum[g * 64 + tid];
        cinv[tid] = 1.f / s;
    }
    __syncthreads();

    float rinv[2][2];
    #pragma unroll
    for (int mi = 0; mi < 2; ++mi)
        #pragma unroll
        for (int h = 0; h < 2; ++h) rinv[mi][h] = cinv[32*wt + 16*mi + r + 8*h];

    // stage normalized values transposed: stage[s][t], stride 68 floats
    float* stage = (float*)(smem + SM_B);
    #pragma unroll
    for (int mi = 0; mi < 2; ++mi)
        #pragma unroll
        for (int ni = 0; ni < 8; ++ni)
            #pragma unroll
            for (int c = 0; c < 4; ++c) {
                int h = c >> 1, p = c & 1;
                int s = 64*ws + 8*ni + 2*q + p;
                int t = 32*wt + 16*mi + r + 8*h;
                stage[s * 68 + t] = acc[mi][ni][c] * rinv[mi][h];
            }
    __syncthreads();

    // coalesced store: 512 s-columns x 64 t floats
    float* outb = out + (size_t)b * SZ * TLEN + tb;
    #pragma unroll
    for (int i = 0; i < 16; ++i) {
        int idx = i * 512 + tid;
        int ss = idx >> 4, f4 = idx & 15;
        float4 v = *reinterpret_cast<const float4*>(&stage[ss * 68 + f4 * 4]);
        *reinterpret_cast<float4*>(&outb[(size_t)ss * TLEN + f4 * 4]) = v;
    }
}

extern "C" void kernel_launch(void* const* d_in, const int* in_sizes, int n_in,
                              void* d_out, int out_size) {
    const float* H     = (const float*)d_in[0];
    const float* units = (const float*)d_in[1];
    float* out = (float*)d_out;

    cudaFuncSetAttribute(mb_kernel, cudaFuncAttributeMaxDynamicSharedMemorySize, SM_TOTAL);

    prep_kernel<<<512, 128>>>(units);
    dim3 grid(TLEN / 64, BATCH);
    mb_kernel<<<grid, 512, SM_TOTAL>>>(H, out);
}

// round 11
// speedup vs baseline: 1.2437x; 1.2437x over previous
#include <cuda_runtime.h>
#include <cuda_fp16.h>
#include <cstdint>

#define BATCH 32
#define DIM   128
#define TLEN  4096
#define SZ    512

// ---- smem byte map (per CTA, ~104 KB for 2 CTAs/SM) ----
#define SM_MBFX  0
#define SM_MBFY  8
#define SM_MBEX  16
#define SM_MBEY  24
#define SM_M2    128      // 512 floats  -> ends 2176
#define SM_PSUM  2176     // 8*32 floats -> ends 3200
#define SM_CINV  3200     // 32 floats   -> ends 3328
#define SM_A     3456     // [2 comp][128 k][40 halfs=80B]; hi @0, lo @+10240 -> 20480 B
#define SM_B     24064    // X @0 (40960), Y @+40960  -> 81920 B
#define SM_TOTAL 105984
// epilogue stage reuses SM_B: [512 s][36 floats] = 73728 B

// global prep images: [4 kc][2 comp][512 s][40 halfs]  (comp-hi @0, comp-lo @+40960 per kc)
__device__ __align__(128) unsigned char gUimgB[327680];
__device__ float g_m2[SZ];

__device__ __forceinline__ uint32_t smem_u32(const void* p) {
    uint32_t a;
    asm("{ .reg .u64 t; cvta.to.shared.u64 t, %1; cvt.u32.u64 %0, t; }" : "=r"(a) : "l"(p));
    return a;
}
#define MBAR_INIT(a,n)   asm volatile("mbarrier.init.shared.b64 [%0], %1;" ::"r"(a),"r"(n):"memory")
#define MBAR_EXPECT(a,b) asm volatile("mbarrier.arrive.expect_tx.shared.b64 _, [%0], %1;" ::"r"(a),"r"(b):"memory")
#define MBAR_ARRIVE(a)   asm volatile("mbarrier.arrive.release.cta.shared::cta.b64 _, [%0];" ::"r"(a):"memory")
__device__ __forceinline__ void mbar_wait(uint32_t mbar, uint32_t parity) {
    uint32_t done;
    asm volatile("{ .reg .pred p; mbarrier.try_wait.parity.acquire.cta.shared::cta.b64 p, [%1], %2; selp.b32 %0,1,0,p; }"
                 : "=r"(done) : "r"(mbar), "r"(parity) : "memory");
    if (!done) {
        asm volatile("{ .reg .pred P1; W_%=: mbarrier.try_wait.parity.acquire.cta.shared::cta.b64 P1, [%0], %1, 0x989680;\n\t"
                     "@P1 bra.uni D_%=; bra.uni W_%=; D_%=: }" :: "r"(mbar), "r"(parity) : "memory");
    }
}
__device__ __forceinline__ void bulk_g2s(uint32_t dst, const void* src, uint32_t bytes, uint32_t mbar) {
    uint64_t g = (uint64_t)__cvta_generic_to_global(src);
    asm volatile("cp.async.bulk.shared::cta.global.mbarrier::complete_tx::bytes [%0], [%1], %2, [%3];"
                 :: "r"(dst), "l"(g), "r"(bytes), "r"(mbar) : "memory");
}
__device__ __forceinline__ void ldsm4t(uint32_t* r, uint32_t a) {
    asm volatile("ldmatrix.sync.aligned.m8n8.x4.trans.shared.b16 {%0,%1,%2,%3}, [%4];"
                 : "=r"(r[0]),"=r"(r[1]),"=r"(r[2]),"=r"(r[3]) : "r"(a));
}
__device__ __forceinline__ void ldsm4(uint32_t* r, uint32_t a) {
    asm volatile("ldmatrix.sync.aligned.m8n8.x4.shared.b16 {%0,%1,%2,%3}, [%4];"
                 : "=r"(r[0]),"=r"(r[1]),"=r"(r[2]),"=r"(r[3]) : "r"(a));
}
__device__ __forceinline__ void mma16816(float* d, const uint32_t* a, const uint32_t* b) {
    asm volatile("mma.sync.aligned.m16n8k16.row.col.f32.f16.f16.f32 "
                 "{%0,%1,%2,%3}, {%4,%5,%6,%7}, {%8,%9}, {%0,%1,%2,%3};"
                 : "+f"(d[0]),"+f"(d[1]),"+f"(d[2]),"+f"(d[3])
                 : "r"(a[0]),"r"(a[1]),"r"(a[2]),"r"(a[3]), "r"(b[0]),"r"(b[1]));
}

// ---- merged prep: hi/lo image + m2, 512 blocks (one s each) x 128 threads ----
__global__ void prep_kernel(const float* __restrict__ units) {
    const int s = blockIdx.x, k = threadIdx.x;
    const int lane = k & 31;
    float x = units[k * SZ + s];
    __half hi = __float2half_rn(x);
    __half lo = __float2half_rn(x - __half2float(hi));
    int kc = k >> 5, kl = k & 31;
    __half* base = (__half*)gUimgB;
    base[((kc * 2 + 0) * 512 + s) * 40 + kl] = hi;
    base[((kc * 2 + 1) * 512 + s) * 40 + kl] = lo;

    float v = x * x;
    #pragma unroll
    for (int o = 16; o > 0; o >>= 1) v += __shfl_xor_sync(0xffffffffu, v, o);
    __shared__ float ps[4];
    if (lane == 0) ps[k >> 5] = v;
    __syncthreads();
    if (k == 0) g_m2[s] = ps[0] + ps[1] + ps[2] + ps[3];
}

__global__ __launch_bounds__(256, 2)
void mb_kernel(const float* __restrict__ H, float* __restrict__ out) {
    extern __shared__ __align__(128) unsigned char smem[];
    const uint32_t sb = smem_u32(smem);
    const int tid = threadIdx.x, w = tid >> 5, lane = tid & 31;
    const int r = lane >> 2, q = lane & 3;
    const int b = blockIdx.y, tb = blockIdx.x * 32;

    if (tid == 0) {
        MBAR_INIT(sb + SM_MBFX, 1);
        MBAR_INIT(sb + SM_MBFY, 1);
        MBAR_INIT(sb + SM_MBEX, 8);
        MBAR_INIT(sb + SM_MBEY, 8);
        // pre-load kc=0: Bh -> X, Bl -> Y (40960 B each)
        MBAR_EXPECT(sb + SM_MBFX, 40960);
        bulk_g2s(sb + SM_B,         gUimgB,         40960, sb + SM_MBFX);
        MBAR_EXPECT(sb + SM_MBFY, 40960);
        bulk_g2s(sb + SM_B + 40960, gUimgB + 40960, 40960, sb + SM_MBFY);
    }

    // m2 -> smem
    ((float*)(smem + SM_M2))[tid]       = g_m2[tid];
    ((float*)(smem + SM_M2))[tid + 256] = g_m2[tid + 256];

    // ---- H tile (128 k x 32 t fp32) -> split f16 hi/lo -> A smem [comp][k][40h] ----
    const float* Hb = H + (size_t)b * DIM * TLEN;
    #pragma unroll
    for (int i = 0; i < 4; ++i) {
        int f4 = i * 256 + tid;          // 0..1023
        int k = f4 >> 3, t0 = (f4 & 7) * 4;
        float4 v = *reinterpret_cast<const float4*>(&Hb[(size_t)k * TLEN + tb + t0]);
        float xs[4] = {v.x, v.y, v.z, v.w};
        uint32_t hiw[2], low[2];
        #pragma unroll
        for (int j = 0; j < 2; ++j) {
            __half h0 = __float2half_rn(xs[2*j]);
            __half h1 = __float2half_rn(xs[2*j+1]);
            __half l0 = __float2half_rn(xs[2*j]   - __half2float(h0));
            __half l1 = __float2half_rn(xs[2*j+1] - __half2float(h1));
            hiw[j] = (uint32_t)__half_as_ushort(h0) | ((uint32_t)__half_as_ushort(h1) << 16);
            low[j] = (uint32_t)__half_as_ushort(l0) | ((uint32_t)__half_as_ushort(l1) << 16);
        }
        *reinterpret_cast<uint2*>(smem + SM_A +         k * 80 + t0 * 2) = make_uint2(hiw[0], hiw[1]);
        *reinterpret_cast<uint2*>(smem + SM_A + 10240 + k * 80 + t0 * 2) = make_uint2(low[0], low[1]);
    }
    __syncthreads();   // A visible + mbarriers initialized

    // ---- MMA main loop: warp tile = 32 t x 64 s; per kc: (p0+p2 on Bh) then (p1 on Bl) ----
    float acc[2][8][4];
    #pragma unroll
    for (int mi = 0; mi < 2; ++mi)
        #pragma unroll
        for (int ni = 0; ni < 8; ++ni)
            #pragma unroll
            for (int c = 0; c < 4; ++c) acc[mi][ni][c] = 0.f;

    const int lr = lane & 7;
    const uint32_t kAdd = (lane & 16) ? 8u : 0u;
    const uint32_t g1   = (lane & 8)  ? 8u : 0u;
    const uint32_t bufX = sb + SM_B, bufY = sb + SM_B + 40960;

    #pragma unroll 1
    for (int kc = 0; kc < 4; ++kc) {
        const uint32_t par = kc & 1;

        // ---- phase A: Bh resident in X -> p0 (Ah*Bh) + p2 (Al*Bh) ----
        mbar_wait(sb + SM_MBFX, par);
        #pragma unroll
        for (int ks = 0; ks < 2; ++ks) {
            const int k0g = kc * 32 + ks * 16;
            const int kl0 = ks * 16;
            uint32_t afh[2][4], afl[2][4], bfh[4][4];
            #pragma unroll
            for (int mi = 0; mi < 2; ++mi)
                ldsm4t(afh[mi], sb + SM_A + (k0g + lr + kAdd) * 80 + (16*mi + g1) * 2);
            #pragma unroll
            for (int j = 0; j < 4; ++j)
                ldsm4(bfh[j], bufX + (64*w + 16*j + lr + kAdd) * 80 + (kl0 + g1) * 2);
            #pragma unroll
            for (int mi = 0; mi < 2; ++mi)
                #pragma unroll
                for (int j = 0; j < 4; ++j) {
                    mma16816(acc[mi][2*j],     afh[mi], &bfh[j][0]);
                    mma16816(acc[mi][2*j + 1], afh[mi], &bfh[j][2]);
                }
            #pragma unroll
            for (int mi = 0; mi < 2; ++mi)
                ldsm4t(afl[mi], sb + SM_A + 10240 + (k0g + lr + kAdd) * 80 + (16*mi + g1) * 2);
            #pragma unroll
            for (int mi = 0; mi < 2; ++mi)
                #pragma unroll
                for (int j = 0; j < 4; ++j) {
                    mma16816(acc[mi][2*j],     afl[mi], &bfh[j][0]);
                    mma16816(acc[mi][2*j + 1], afl[mi], &bfh[j][2]);
                }
        }
        if (lane == 0) MBAR_ARRIVE(sb + SM_MBEX);
        if (tid == 0 && kc < 3) {
            mbar_wait(sb + SM_MBEX, par);
            MBAR_EXPECT(sb + SM_MBFX, 40960);
            bulk_g2s(bufX, gUimgB + (kc + 1) * 81920, 40960, sb + SM_MBFX);
        }

        // ---- phase B: Bl resident in Y -> p1 (Ah*Bl) ----
        mbar_wait(sb + SM_MBFY, par);
        #pragma unroll
        for (int ks = 0; ks < 2; ++ks) {
            const int k0g = kc * 32 + ks * 16;
            const int kl0 = ks * 16;
            uint32_t afh[2][4], bfl[4][4];
            #pragma unroll
            for (int mi = 0; mi < 2; ++mi)
                ldsm4t(afh[mi], sb + SM_A + (k0g + lr + kAdd) * 80 + (16*mi + g1) * 2);
            #pragma unroll
            for (int j = 0; j < 4; ++j)
                ldsm4(bfl[j], bufY + (64*w + 16*j + lr + kAdd) * 80 + (kl0 + g1) * 2);
            #pragma unroll
            for (int mi = 0; mi < 2; ++mi)
                #pragma unroll
                for (int j = 0; j < 4; ++j) {
                    mma16816(acc[mi][2*j],     afh[mi], &bfl[j][0]);
                    mma16816(acc[mi][2*j + 1], afh[mi], &bfl[j][2]);
                }
        }
        if (lane == 0) MBAR_ARRIVE(sb + SM_MBEY);
        if (tid == 0 && kc < 3) {
            mbar_wait(sb + SM_MBEY, par);
            MBAR_EXPECT(sb + SM_MBFY, 40960);
            bulk_g2s(bufY, gUimgB + (kc + 1) * 81920 + 40960, 40960, sb + SM_MBFY);
        }
    }

    // ---- epilogue: exp (no max-sub; |logit| bounded) -> sum over s -> scale ----
    const float* m2s = (const float*)(smem + SM_M2);
    float* psum = (float*)(smem + SM_PSUM);
    float* cinv = (float*)(smem + SM_CINV);

    float m2v[8][2];
    #pragma unroll
    for (int ni = 0; ni < 8; ++ni) {
        m2v[ni][0] = m2s[64*w + 8*ni + 2*q];
        m2v[ni][1] = m2s[64*w + 8*ni + 2*q + 1];
    }

    #pragma unroll
    for (int mi = 0; mi < 2; ++mi)
        #pragma unroll
        for (int h = 0; h < 2; ++h) {
            float s = 0.f;
            #pragma unroll
            for (int ni = 0; ni < 8; ++ni) {
                float e0 = __expf(fmaf(2.f, acc[mi][ni][2*h],     -m2v[ni][0]));
                float e1 = __expf(fmaf(2.f, acc[mi][ni][2*h + 1], -m2v[ni][1]));
                acc[mi][ni][2*h] = e0; acc[mi][ni][2*h + 1] = e1;
                s += e0 + e1;
            }
            s += __shfl_xor_sync(0xffffffffu, s, 1);
            s += __shfl_xor_sync(0xffffffffu, s, 2);
            if (q == 0) psum[w * 32 + 16*mi + r + 8*h] = s;
        }
    __syncthreads();   // all warps finished mainloop + psum visible
    if (tid < 32) {
        float s = psum[tid];
        #pragma unroll
        for (int g = 1; g < 8; ++g) s += psum[g * 32 + tid];
        cinv[tid] = 1.f / s;
    }
    __syncthreads();

    float rinv[2][2];
    #pragma unroll
    for (int mi = 0; mi < 2; ++mi)
        #pragma unroll
        for (int h = 0; h < 2; ++h) rinv[mi][h] = cinv[16*mi + r + 8*h];

    // stage normalized values transposed: stage[s][t], stride 36 floats (reuses B region)
    float* stage = (float*)(smem + SM_B);
    #pragma unroll
    for (int mi = 0; mi < 2; ++mi)
        #pragma unroll
        for (int ni = 0; ni < 8; ++ni)
            #pragma unroll
            for (int c = 0; c < 4; ++c) {
                int h = c >> 1, p = c & 1;
                int s = 64*w + 8*ni + 2*q + p;
                int t = 16*mi + r + 8*h;
                stage[s * 36 + t] = acc[mi][ni][c] * rinv[mi][h];
            }
    __syncthreads();

    // coalesced store: 512 s-columns x 32 t floats
    float* outb = out + (size_t)b * SZ * TLEN + tb;
    #pragma unroll
    for (int i = 0; i < 16; ++i) {
        int idx = i * 256 + tid;         // 0..4095 float4s
        int ss = idx >> 3, f4 = idx & 7;
        float4 v = *reinterpret_cast<const float4*>(&stage[ss * 36 + f4 * 4]);
        *reinterpret_cast<float4*>(&outb[(size_t)ss * TLEN + f4 * 4]) = v;
    }
}

extern "C" void kernel_launch(void* const* d_in, const int* in_sizes, int n_in,
                              void* d_out, int out_size) {
    const float* H     = (const float*)d_in[0];
    const float* units = (const float*)d_in[1];
    float* out = (float*)d_out;

    cudaFuncSetAttribute(mb_kernel, cudaFuncAttributeMaxDynamicSharedMemorySize, SM_TOTAL);

    prep_kernel<<<512, 128>>>(units);
    dim3 grid(TLEN / 32, BATCH);
    mb_kernel<<<grid, 256, SM_TOTAL>>>(H, out);
}

// round 12
// speedup vs baseline: 1.3196x; 1.0610x over previous
#include <cuda_runtime.h>
#include <cuda_fp16.h>
#include <cstdint>

#define BATCH 32
#define DIM   128
#define TLEN  4096
#define SZ    512

// ---- smem byte map (per CTA, 89.6 KB -> 2 CTAs/SM) ----
#define SM_MBFX  0
#define SM_MBFY  8
#define SM_MBEX  16
#define SM_MBEY  24
#define SM_M2    128      // 512 floats  -> ends 2176
#define SM_PSUM  2176     // 8*32 floats -> ends 3200
#define SM_CINV  3200     // 32 floats   -> ends 3328
#define SM_A     3456     // [2 comp][128 k][40 halfs=80B]; hi @0, lo @+10240 -> 20480 B
#define SM_B     24064    // X @0 (32768), Y @+32768  -> 65536 B
#define SM_TOTAL 89600

// global prep image: [4 kc][2 comp][512 s][64 B swizzled row] = 262144 B
// element (kc,comp,s,kl) @ ((kc*2+comp)*512+s)*64 + (((kl>>3)^(s>>1))&3)*16 + (kl&7)*2
__device__ __align__(128) unsigned char gUimgB[262144];
__device__ float g_m2[SZ];

__device__ __forceinline__ uint32_t smem_u32(const void* p) {
    uint32_t a;
    asm("{ .reg .u64 t; cvta.to.shared.u64 t, %1; cvt.u32.u64 %0, t; }" : "=r"(a) : "l"(p));
    return a;
}
#define MBAR_INIT(a,n)   asm volatile("mbarrier.init.shared.b64 [%0], %1;" ::"r"(a),"r"(n):"memory")
#define MBAR_EXPECT(a,b) asm volatile("mbarrier.arrive.expect_tx.shared.b64 _, [%0], %1;" ::"r"(a),"r"(b):"memory")
#define MBAR_ARRIVE(a)   asm volatile("mbarrier.arrive.release.cta.shared::cta.b64 _, [%0];" ::"r"(a):"memory")
__device__ __forceinline__ void mbar_wait(uint32_t mbar, uint32_t parity) {
    uint32_t done;
    asm volatile("{ .reg .pred p; mbarrier.try_wait.parity.acquire.cta.shared::cta.b64 p, [%1], %2; selp.b32 %0,1,0,p; }"
                 : "=r"(done) : "r"(mbar), "r"(parity) : "memory");
    if (!done) {
        asm volatile("{ .reg .pred P1; W_%=: mbarrier.try_wait.parity.acquire.cta.shared::cta.b64 P1, [%0], %1, 0x989680;\n\t"
                     "@P1 bra.uni D_%=; bra.uni W_%=; D_%=: }" :: "r"(mbar), "r"(parity) : "memory");
    }
}
__device__ __forceinline__ void bulk_g2s(uint32_t dst, const void* src, uint32_t bytes, uint32_t mbar) {
    uint64_t g = (uint64_t)__cvta_generic_to_global(src);
    asm volatile("cp.async.bulk.shared::cta.global.mbarrier::complete_tx::bytes [%0], [%1], %2, [%3];"
                 :: "r"(dst), "l"(g), "r"(bytes), "r"(mbar) : "memory");
}
__device__ __forceinline__ void ldsm4t(uint32_t* r, uint32_t a) {
    asm volatile("ldmatrix.sync.aligned.m8n8.x4.trans.shared.b16 {%0,%1,%2,%3}, [%4];"
                 : "=r"(r[0]),"=r"(r[1]),"=r"(r[2]),"=r"(r[3]) : "r"(a));
}
__device__ __forceinline__ void ldsm4(uint32_t* r, uint32_t a) {
    asm volatile("ldmatrix.sync.aligned.m8n8.x4.shared.b16 {%0,%1,%2,%3}, [%4];"
                 : "=r"(r[0]),"=r"(r[1]),"=r"(r[2]),"=r"(r[3]) : "r"(a));
}
__device__ __forceinline__ void mma16816(float* d, const uint32_t* a, const uint32_t* b) {
    asm volatile("mma.sync.aligned.m16n8k16.row.col.f32.f16.f16.f32 "
                 "{%0,%1,%2,%3}, {%4,%5,%6,%7}, {%8,%9}, {%0,%1,%2,%3};"
                 : "+f"(d[0]),"+f"(d[1]),"+f"(d[2]),"+f"(d[3])
                 : "r"(a[0]),"r"(a[1]),"r"(a[2]),"r"(a[3]), "r"(b[0]),"r"(b[1]));
}

// swizzled byte offset within a chunk for element (s, kl)
__host__ __device__ __forceinline__ int bswz(int s, int kl) {
    return s * 64 + ((((kl >> 3) ^ (s >> 1)) & 3) << 4) + (kl & 7) * 2;
}

// ---- merged prep: swizzled hi/lo image + m2, 512 blocks (one s each) x 128 threads ----
__global__ void prep_kernel(const float* __restrict__ units) {
    const int s = blockIdx.x, k = threadIdx.x;
    const int lane = k & 31;
    float x = units[k * SZ + s];
    __half hi = __float2half_rn(x);
    __half lo = __float2half_rn(x - __half2float(hi));
    int kc = k >> 5, kl = k & 31;
    int sw = bswz(s, kl);
    *(__half*)(gUimgB + (size_t)(kc * 2 + 0) * 32768 + sw) = hi;
    *(__half*)(gUimgB + (size_t)(kc * 2 + 1) * 32768 + sw) = lo;

    float v = x * x;
    #pragma unroll
    for (int o = 16; o > 0; o >>= 1) v += __shfl_xor_sync(0xffffffffu, v, o);
    __shared__ float ps[4];
    if (lane == 0) ps[k >> 5] = v;
    __syncthreads();
    if (k == 0) g_m2[s] = ps[0] + ps[1] + ps[2] + ps[3];
}

__global__ __launch_bounds__(256, 2)
void mb_kernel(const float* __restrict__ H, float* __restrict__ out) {
    extern __shared__ __align__(128) unsigned char smem[];
    const uint32_t sb = smem_u32(smem);
    const int tid = threadIdx.x, w = tid >> 5, lane = tid & 31;
    const int r = lane >> 2, q = lane & 3;
    const int b = blockIdx.y, tb = blockIdx.x * 32;

    if (tid == 0) {
        MBAR_INIT(sb + SM_MBFX, 1);
        MBAR_INIT(sb + SM_MBFY, 1);
        MBAR_INIT(sb + SM_MBEX, 8);
        MBAR_INIT(sb + SM_MBEY, 8);
        // pre-load kc=0: Bh -> X, Bl -> Y (32768 B each)
        MBAR_EXPECT(sb + SM_MBFX, 32768);
        bulk_g2s(sb + SM_B,         gUimgB,         32768, sb + SM_MBFX);
        MBAR_EXPECT(sb + SM_MBFY, 32768);
        bulk_g2s(sb + SM_B + 32768, gUimgB + 32768, 32768, sb + SM_MBFY);
    }

    // m2 -> smem
    ((float*)(smem + SM_M2))[tid]       = g_m2[tid];
    ((float*)(smem + SM_M2))[tid + 256] = g_m2[tid + 256];

    // ---- H tile (128 k x 32 t fp32) -> split f16 hi/lo -> A smem [comp][k][40h] ----
    const float* Hb = H + (size_t)b * DIM * TLEN;
    #pragma unroll
    for (int i = 0; i < 4; ++i) {
        int f4 = i * 256 + tid;          // 0..1023
        int k = f4 >> 3, t0 = (f4 & 7) * 4;
        float4 v = *reinterpret_cast<const float4*>(&Hb[(size_t)k * TLEN + tb + t0]);
        float xs[4] = {v.x, v.y, v.z, v.w};
        uint32_t hiw[2], low[2];
        #pragma unroll
        for (int j = 0; j < 2; ++j) {
            __half h0 = __float2half_rn(xs[2*j]);
            __half h1 = __float2half_rn(xs[2*j+1]);
            __half l0 = __float2half_rn(xs[2*j]   - __half2float(h0));
            __half l1 = __float2half_rn(xs[2*j+1] - __half2float(h1));
            hiw[j] = (uint32_t)__half_as_ushort(h0) | ((uint32_t)__half_as_ushort(h1) << 16);
            low[j] = (uint32_t)__half_as_ushort(l0) | ((uint32_t)__half_as_ushort(l1) << 16);
        }
        *reinterpret_cast<uint2*>(smem + SM_A +         k * 80 + t0 * 2) = make_uint2(hiw[0], hiw[1]);
        *reinterpret_cast<uint2*>(smem + SM_A + 10240 + k * 80 + t0 * 2) = make_uint2(low[0], low[1]);
    }
    __syncthreads();   // A visible + mbarriers initialized

    // ---- MMA main loop: warp tile = 32 t x 64 s; per kc: (p0+p2 on Bh) then (p1 on Bl) ----
    float acc[2][8][4];
    #pragma unroll
    for (int mi = 0; mi < 2; ++mi)
        #pragma unroll
        for (int ni = 0; ni < 8; ++ni)
            #pragma unroll
            for (int c = 0; c < 4; ++c) acc[mi][ni][c] = 0.f;

    const int lr = lane & 7;
    const uint32_t kAdd = (lane & 16) ? 8u : 0u;
    const uint32_t g1   = (lane & 8)  ? 8u : 0u;
    const uint32_t bufX = sb + SM_B, bufY = sb + SM_B + 32768;

    #pragma unroll 1
    for (int kc = 0; kc < 4; ++kc) {
        const uint32_t par = kc & 1;

        // ---- phase A: Bh resident in X -> p0 (Ah*Bh) + p2 (Al*Bh) ----
        mbar_wait(sb + SM_MBFX, par);
        #pragma unroll
        for (int ks = 0; ks < 2; ++ks) {
            const int k0g = kc * 32 + ks * 16;
            const int kl0 = ks * 16;
            const int c16 = (kl0 + (int)g1) >> 3;
            uint32_t afh[2][4], afl[2][4], bfh[4][4];
            #pragma unroll
            for (int mi = 0; mi < 2; ++mi)
                ldsm4t(afh[mi], sb + SM_A + (k0g + lr + kAdd) * 80 + (16*mi + g1) * 2);
            #pragma unroll
            for (int j = 0; j < 4; ++j) {
                int row = 64*w + 16*j + lr + (int)kAdd;
                ldsm4(bfh[j], bufX + row * 64 + ((((c16) ^ (row >> 1)) & 3) << 4));
            }
            #pragma unroll
            for (int mi = 0; mi < 2; ++mi)
                #pragma unroll
                for (int j = 0; j < 4; ++j) {
                    mma16816(acc[mi][2*j],     afh[mi], &bfh[j][0]);
                    mma16816(acc[mi][2*j + 1], afh[mi], &bfh[j][2]);
                }
            #pragma unroll
            for (int mi = 0; mi < 2; ++mi)
                ldsm4t(afl[mi], sb + SM_A + 10240 + (k0g + lr + kAdd) * 80 + (16*mi + g1) * 2);
            #pragma unroll
            for (int mi = 0; mi < 2; ++mi)
                #pragma unroll
                for (int j = 0; j < 4; ++j) {
                    mma16816(acc[mi][2*j],     afl[mi], &bfh[j][0]);
                    mma16816(acc[mi][2*j + 1], afl[mi], &bfh[j][2]);
                }
        }
        if (lane == 0) MBAR_ARRIVE(sb + SM_MBEX);
        if (tid == 0 && kc < 3) {
            mbar_wait(sb + SM_MBEX, par);
            MBAR_EXPECT(sb + SM_MBFX, 32768);
            bulk_g2s(bufX, gUimgB + (size_t)(kc + 1) * 65536, 32768, sb + SM_MBFX);
        }

        // ---- phase B: Bl resident in Y -> p1 (Ah*Bl) ----
        mbar_wait(sb + SM_MBFY, par);
        #pragma unroll
        for (int ks = 0; ks < 2; ++ks) {
            const int k0g = kc * 32 + ks * 16;
            const int kl0 = ks * 16;
            const int c16 = (kl0 + (int)g1) >> 3;
            uint32_t afh[2][4], bfl[4][4];
            #pragma unroll
            for (int mi = 0; mi < 2; ++mi)
                ldsm4t(afh[mi], sb + SM_A + (k0g + lr + kAdd) * 80 + (16*mi + g1) * 2);
            #pragma unroll
            for (int j = 0; j < 4; ++j) {
                int row = 64*w + 16*j + lr + (int)kAdd;
                ldsm4(bfl[j], bufY + row * 64 + ((((c16) ^ (row >> 1)) & 3) << 4));
            }
            #pragma unroll
            for (int mi = 0; mi < 2; ++mi)
                #pragma unroll
                for (int j = 0; j < 4; ++j) {
                    mma16816(acc[mi][2*j],     afh[mi], &bfl[j][0]);
                    mma16816(acc[mi][2*j + 1], afh[mi], &bfl[j][2]);
                }
        }
        if (lane == 0) MBAR_ARRIVE(sb + SM_MBEY);
        if (tid == 0 && kc < 3) {
            mbar_wait(sb + SM_MBEY, par);
            MBAR_EXPECT(sb + SM_MBFY, 32768);
            bulk_g2s(bufY, gUimgB + (size_t)(kc + 1) * 65536 + 32768, 32768, sb + SM_MBFY);
        }
    }

    // ---- epilogue: exp (no max-sub; |logit| bounded) -> sum over s -> scale -> direct STG ----
    const float* m2s = (const float*)(smem + SM_M2);
    float* psum = (float*)(smem + SM_PSUM);
    float* cinv = (float*)(smem + SM_CINV);

    float m2v[8][2];
    #pragma unroll
    for (int ni = 0; ni < 8; ++ni) {
        m2v[ni][0] = m2s[64*w + 8*ni + 2*q];
        m2v[ni][1] = m2s[64*w + 8*ni + 2*q + 1];
    }

    #pragma unroll
    for (int mi = 0; mi < 2; ++mi)
        #pragma unroll
        for (int h = 0; h < 2; ++h) {
            float s = 0.f;
            #pragma unroll
            for (int ni = 0; ni < 8; ++ni) {
                float e0 = __expf(fmaf(2.f, acc[mi][ni][2*h],     -m2v[ni][0]));
                float e1 = __expf(fmaf(2.f, acc[mi][ni][2*h + 1], -m2v[ni][1]));
                acc[mi][ni][2*h] = e0; acc[mi][ni][2*h + 1] = e1;
                s += e0 + e1;
            }
            s += __shfl_xor_sync(0xffffffffu, s, 1);
            s += __shfl_xor_sync(0xffffffffu, s, 2);
            if (q == 0) psum[w * 32 + 16*mi + r + 8*h] = s;
        }
    __syncthreads();   // all warps finished mainloop + psum visible
    if (tid < 32) {
        float s = psum[tid];
        #pragma unroll
        for (int g = 1; g < 8; ++g) s += psum[g * 32 + tid];
        cinv[tid] = 1.f / s;
    }
    __syncthreads();

    float rinv[2][2];
    #pragma unroll
    for (int mi = 0; mi < 2; ++mi)
        #pragma unroll
        for (int h = 0; h < 2; ++h) rinv[mi][h] = cinv[16*mi + r + 8*h];

    // direct store: lanes r give 8 consecutive t -> full 32B sectors
    float* outb = out + (size_t)b * SZ * TLEN + tb;
    #pragma unroll
    for (int mi = 0; mi < 2; ++mi)
        #pragma unroll
        for (int ni = 0; ni < 8; ++ni)
            #pragma unroll
            for (int c = 0; c < 4; ++c) {
                int s = 64*w + 8*ni + 2*q + (c & 1);
                int t = 16*mi + r + 8*(c >> 1);
                outb[(size_t)s * TLEN + t] = acc[mi][ni][c] * rinv[mi][c >> 1];
            }
}

extern "C" void kernel_launch(void* const* d_in, const int* in_sizes, int n_in,
                              void* d_out, int out_size) {
    const float* H     = (const float*)d_in[0];
    const float* units = (const float*)d_in[1];
    float* out = (float*)d_out;

    cudaFuncSetAttribute(mb_kernel, cudaFuncAttributeMaxDynamicSharedMemorySize, SM_TOTAL);

    prep_kernel<<<512, 128>>>(units);
    dim3 grid(TLEN / 32, BATCH);
    mb_kernel<<<grid, 256, SM_TOTAL>>>(H, out);
}